// round 1
// baseline (speedup 1.0000x reference)
#include <cuda_runtime.h>

// FastIMDCT4: B=32, T=1024, n_fft=2048, hop=1024.
// signal: (32, 1024, 1024) f32, window: (2048,) f32
// out: (32, 1, 1, 1047552) f32, y[b, 1024*t + r] = frames[t][1024+r] + frames[t+1][r]

static constexpr int T_FRAMES = 1024;
static constexpr int OUTW     = 1023 * 1024;   // 1047552 per batch

__device__ __forceinline__ float2 cmul(float2 a, float2 b) {
    return make_float2(a.x * b.x - a.y * b.y, a.x * b.y + a.y * b.x);
}

// idx permutation from the reference, closed form (n_fft = 2048):
//   i < 1024:  even -> i,        odd -> 1024 - i
//   i >= 1024: even -> i - 1023, odd -> 2047 - i
__device__ __forceinline__ int idx_fn(int i) {
    if (i < 1024) return (i & 1) ? (1024 - i) : i;
    return (i & 1) ? (2047 - i) : (i - 1023);
}

__global__ __launch_bounds__(512)
void imdct_kernel(const float* __restrict__ sig,
                  const float* __restrict__ win,
                  float* __restrict__ out)
{
    const int t    = blockIdx.x;     // 0..1022
    const int b    = blockIdx.y;     // 0..31
    const int tid  = threadIdx.x;    // 0..511
    const int sub  = tid >> 8;       // which FFT: frame t+sub
    const int stid = tid & 255;      // thread within that FFT

    // [fft][pingpong][elem] : 16 KB, + 2 KB twiddle table
    __shared__ float2 buf[2][2][512];
    __shared__ float2 wtab[256];     // wtab[i] = exp(-2*pi*i*i_unit/512)

    if (tid < 256) {
        float sn, cs;
        sincosf(-6.283185307179586f * (float)tid * (1.0f / 512.0f), &sn, &cs);
        wtab[tid] = make_float2(cs, sn);
    }

    // ---- load + pre-twiddle:  c[k] = (sig[2k] + i*sig[1023-2k]) * tw[k] ----
    const float* sp = sig + ((size_t)(b * T_FRAMES + (t + sub))) * 1024;
    float twc[2], tws[2];   // cache tw[k] for reuse in post-twiddle
    #pragma unroll
    for (int q = 0; q < 2; q++) {
        int k = stid + (q << 8);
        float re = sp[2 * k];
        float im = sp[1023 - 2 * k];
        float sn, cs;
        sincosf(-6.283185307179586f * ((float)k + 0.125f) * (1.0f / 2048.0f), &sn, &cs);
        twc[q] = cs; tws[q] = sn;
        buf[sub][0][k] = make_float2(re * cs - im * sn, re * sn + im * cs);
    }
    __syncthreads();

    // ---- 512-pt forward FFT, Stockham autosort, 9 radix-2 stages ----
    int pp = 0;
    #pragma unroll
    for (int s = 0; s < 9; s++) {
        const int m = 1 << s;
        const int j = stid >> s;               // stid = j*m + k
        float2 c0 = buf[sub][pp][stid];
        float2 c1 = buf[sub][pp][stid + 256];
        float2 w  = wtab[j << s];              // exp(-2*pi*i*j/(2l)), 2l = 512>>s
        float2 d0 = make_float2(c0.x + c1.x, c0.y + c1.y);
        float2 e  = make_float2(c0.x - c1.x, c0.y - c1.y);
        float2 d1 = cmul(e, w);
        const int o  = stid + j * m;           // = k + 2*j*m
        const int np = pp ^ 1;
        buf[sub][np][o]     = d0;
        buf[sub][np][o + m] = d1;
        pp = np;
        __syncthreads();
    }
    // pp == 1 now holds the DFT in natural order.

    // ---- post-twiddle (same tw[k], cached in registers) ----
    #pragma unroll
    for (int q = 0; q < 2; q++) {
        int k = stid + (q << 8);
        float2 v = buf[sub][pp][k];
        buf[sub][pp][k] = make_float2(v.x * twc[q] - v.y * tws[q],
                                      v.x * tws[q] + v.y * twc[q]);
    }
    __syncthreads();

    // ---- permute + window + overlap-add of the two adjacent frames ----
    // inter[2k] = Re c[k], inter[2k+1] = Im c[k]
    // frames[n] = sign[n] * window[n] * inter[idx((n+512)&2047)] / 512
    const float inv = 1.0f / 512.0f;
    float* op = out + (size_t)b * OUTW + (size_t)t * 1024;

    #pragma unroll
    for (int q = 0; q < 2; q++) {
        const int r = tid + (q << 9);          // 0..1023
        float acc = 0.0f;
        #pragma unroll
        for (int f = 0; f < 2; f++) {
            const int n  = (f == 0) ? (1024 + r) : r;   // frame t uses n=1024+r, frame t+1 uses n=r
            const int ii = (n + 512) & 2047;
            const int m_ = idx_fn(ii);
            float2 cv = buf[f][pp][m_ >> 1];
            float val = (m_ & 1) ? cv.y : cv.x;
            // sign = (-1)^{ii odd} * (-1)^{ii < 512}
            bool neg = (((ii & 1) != 0) ^ (ii < 512));
            float v = val * win[n];
            acc += neg ? -v : v;
        }
        op[r] = acc * inv;
    }
}

extern "C" void kernel_launch(void* const* d_in, const int* in_sizes, int n_in,
                              void* d_out, int out_size) {
    const float* sig = (const float*)d_in[0];
    const float* win = (const float*)d_in[1];
    float* out = (float*)d_out;
    dim3 grid(1023, 32);
    imdct_kernel<<<grid, 512>>>(sig, win, out);
}

// round 2
// speedup vs baseline: 2.7959x; 2.7959x over previous
#include <cuda_runtime.h>

// FastIMDCT4: B=32, T=1024, n_fft=2048, hop=1024.
// signal: (32, 1024, 1024) f32, window: (2048,) f32
// out: (32, 1, 1, 1047552) f32, y[b, 1024*t + r] = frames[t][1024+r] + frames[t+1][r]
//
// Per block: 576 threads = 9 FFT groups of 64 threads. Each group does a 512-pt
// complex FFT as 3 radix-8 register stages (8 float2/thread), with 2 padded
// shared-memory exchanges. Block emits 8 output chunks of 1024 floats.

static constexpr int OUTW = 1023 * 1024;   // 1047552 per batch

#define PAD(p) ((p) + ((p) >> 4))

__device__ __forceinline__ float2 cmulf(float2 a, float2 b) {
    return make_float2(a.x * b.x - a.y * b.y, a.x * b.y + a.y * b.x);
}
__device__ __forceinline__ float2 cadd(float2 a, float2 b) { return make_float2(a.x + b.x, a.y + b.y); }
__device__ __forceinline__ float2 csub(float2 a, float2 b) { return make_float2(a.x - b.x, a.y - b.y); }

// idx permutation (n_fft=2048), closed form:
//   i < 1024:  even -> i,        odd -> 1024 - i
//   i >= 1024: even -> i - 1023, odd -> 2047 - i
__device__ __forceinline__ int idx_fn(int i) {
    if (i < 1024) return (i & 1) ? (1024 - i) : i;
    return (i & 1) ? (2047 - i) : (i - 1023);
}

// In-register DFT-8 (forward, W8 = cis(-2pi/8)), Stockham radix-2 x3, natural order.
__device__ __forceinline__ void dft8(const float2* c, float2* y) {
    const float C = 0.70710678118654752440f;
    float2 s;
    float2 d0 = cadd(c[0], c[4]), d1 = csub(c[0], c[4]);
    float2 d2 = cadd(c[1], c[5]); s = csub(c[1], c[5]);
    float2 d3 = make_float2(C * (s.x + s.y), C * (s.y - s.x));          // * W8^1
    float2 d4 = cadd(c[2], c[6]); s = csub(c[2], c[6]);
    float2 d5 = make_float2(s.y, -s.x);                                  // * -i
    float2 d6 = cadd(c[3], c[7]); s = csub(c[3], c[7]);
    float2 d7 = make_float2(C * (s.y - s.x), -C * (s.x + s.y));          // * W8^3

    float2 e0 = cadd(d0, d4), e2 = csub(d0, d4);
    float2 e1 = cadd(d1, d5), e3 = csub(d1, d5);
    float2 e4 = cadd(d2, d6); s = csub(d2, d6);
    float2 e6 = make_float2(s.y, -s.x);                                  // * -i
    float2 e5 = cadd(d3, d7); s = csub(d3, d7);
    float2 e7 = make_float2(s.y, -s.x);                                  // * -i

    y[0] = cadd(e0, e4); y[4] = csub(e0, e4);
    y[1] = cadd(e1, e5); y[5] = csub(e1, e5);
    y[2] = cadd(e2, e6); y[6] = csub(e2, e6);
    y[3] = cadd(e3, e7); y[7] = csub(e3, e7);
}

__global__ __launch_bounds__(576, 2)
void imdct_kernel(const float* __restrict__ sig,
                  const float* __restrict__ win,
                  float* __restrict__ out)
{
    __shared__ float2 fbuf[9][544];   // 9 frames x (512 + pad) complex
    __shared__ float  wsm[2048];      // sign * window / 512

    const int tid = threadIdx.x;
    const int t0  = blockIdx.x * 8;   // first output chunk of this block
    const int b   = blockIdx.y;
    const int fid = tid >> 6;         // FFT group 0..8 -> frame t0+fid
    const int i   = tid & 63;         // lane within FFT group

    // sign * window / 512 (sign: neg iff (ii odd) XOR (ii < 512), ii = (n+512)&2047)
    for (int n = tid; n < 2048; n += 576) {
        int ii = (n + 512) & 2047;
        bool neg = ((ii & 1) != 0) ^ (ii < 512);
        float w = win[n] * (1.0f / 512.0f);
        wsm[n] = neg ? -w : w;
    }

    const int gf = t0 + fid;
    const bool valid = gf < 1024;
    const float* sp = sig + ((size_t)(b * 1024 + (valid ? gf : 0))) * 1024;

    // base twiddle tw[i] = cis(-2pi*(i+0.125)/2048); step per +64: cis(-pi/16)
    float bs, bc;
    __sincosf(-6.283185307179586f * ((float)i + 0.125f) * (1.0f / 2048.0f), &bs, &bc);
    const float2 STEP = make_float2(0.980785280403230449f, -0.195090322016128268f);

    float2 v[8], y[8];

    // ---- load + pre-twiddle: v[r] = (sig[2kk] + i*sig[1023-2kk]) * tw[kk], kk = i + 64r
    {
        float2 tw = make_float2(bc, bs);
        #pragma unroll
        for (int r = 0; r < 8; r++) {
            int kk = i + 64 * r;
            float re = valid ? sp[2 * kk] : 0.0f;
            float im = valid ? sp[1023 - 2 * kk] : 0.0f;
            v[r] = make_float2(re * tw.x - im * tw.y, re * tw.y + im * tw.x);
            tw = cmulf(tw, STEP);
        }
    }

    float2* fb = fbuf[fid];

    // ---- stage 0 (m=1): y = DFT8(v); out[8i + r'] = y[r'] * W512^{i r'}
    dft8(v, y);
    {
        float ws, wc;
        __sincosf(-6.283185307179586f * (float)i * (1.0f / 512.0f), &ws, &wc);
        float2 w1 = make_float2(wc, ws), t = make_float2(1.0f, 0.0f);
        #pragma unroll
        for (int rp = 0; rp < 8; rp++) {
            fb[PAD(8 * i + rp)] = cmulf(y[rp], t);
            t = cmulf(t, w1);
        }
    }
    asm volatile("bar.sync %0, 64;" :: "r"(fid + 1) : "memory");

    // ---- stage 1 (m=8): read stride 64; out[k + 64j + 8r'] = y[r'] * W64^{j r'}
    #pragma unroll
    for (int r = 0; r < 8; r++) v[r] = fb[PAD(i + 64 * r)];
    asm volatile("bar.sync %0, 64;" :: "r"(fid + 1) : "memory");
    dft8(v, y);
    {
        int j = i >> 3, k = i & 7;
        float ws, wc;
        __sincosf(-6.283185307179586f * (float)j * (1.0f / 64.0f), &ws, &wc);
        float2 w1 = make_float2(wc, ws), t = make_float2(1.0f, 0.0f);
        #pragma unroll
        for (int rp = 0; rp < 8; rp++) {
            fb[PAD(k + 64 * j + 8 * rp)] = cmulf(y[rp], t);
            t = cmulf(t, w1);
        }
    }
    asm volatile("bar.sync %0, 64;" :: "r"(fid + 1) : "memory");

    // ---- stage 2 (m=64): read stride 64; X[i + 64r'] = y[r']; fold post-twiddle tw[kk]
    #pragma unroll
    for (int r = 0; r < 8; r++) v[r] = fb[PAD(i + 64 * r)];
    asm volatile("bar.sync %0, 64;" :: "r"(fid + 1) : "memory");
    dft8(v, y);
    {
        float2 tw = make_float2(bc, bs);
        #pragma unroll
        for (int rp = 0; rp < 8; rp++) {
            fb[PAD(i + 64 * rp)] = cmulf(y[rp], tw);
            tw = cmulf(tw, STEP);
        }
    }
    __syncthreads();

    // ---- output: 8 chunks x 1024, each out = frames[t][1024+r] + frames[t+1][r]
    if (tid < 512) {
        float* op = out + (size_t)b * OUTW;
        #pragma unroll
        for (int w = 0; w < 16; w++) {
            int g = w * 512 + tid;
            int cidx = g >> 10;        // chunk 0..7
            int r = g & 1023;
            int t = t0 + cidx;
            if (t > 1022) break;       // cidx nondecreasing in w -> safe to break

            // frame cidx, n = 1024 + r:  ii = (1536 + r) & 2047
            int ii0 = (r < 512) ? (1536 + r) : (r - 512);
            int m0 = idx_fn(ii0);
            float2 c0 = fbuf[cidx][PAD(m0 >> 1)];
            float a0 = (m0 & 1) ? c0.y : c0.x;

            // frame cidx+1, n = r:  ii = r + 512 (no wrap)
            int m1 = idx_fn(r + 512);
            float2 c1 = fbuf[cidx + 1][PAD(m1 >> 1)];
            float a1 = (m1 & 1) ? c1.y : c1.x;

            op[(size_t)t * 1024 + r] = a0 * wsm[1024 + r] + a1 * wsm[r];
        }
    }
}

extern "C" void kernel_launch(void* const* d_in, const int* in_sizes, int n_in,
                              void* d_out, int out_size) {
    const float* sig = (const float*)d_in[0];
    const float* win = (const float*)d_in[1];
    float* out = (float*)d_out;
    dim3 grid(128, 32);
    imdct_kernel<<<grid, 576>>>(sig, win, out);
}

// round 3
// speedup vs baseline: 3.6385x; 1.3014x over previous
#include <cuda_runtime.h>

// FastIMDCT4: B=32, T=1024, n_fft=2048, hop=1024.
// signal: (32, 1024, 1024) f32, window: (2048,) f32
// out: (32, 1, 1, 1047552) f32, y[b, 1024*t + r] = frames[t][1024+r] + frames[t+1][r]
//
// Per block: 576 threads = 9 FFT groups of 64 threads. Each group: 512-pt complex
// FFT, 3 radix-8 register stages, 2 padded smem exchanges. Stage 2 stores inter[]
// in natural m-order (coalesced); output gathers are conflict-free LDS.32 with all
// window/sign/index factors hoisted to registers.

static constexpr int OUTW = 1023 * 1024;

#define PAD(p) ((p) + ((p) >> 4))

__device__ __forceinline__ float2 cmulf(float2 a, float2 b) {
    return make_float2(a.x * b.x - a.y * b.y, a.x * b.y + a.y * b.x);
}
__device__ __forceinline__ float2 cadd(float2 a, float2 b) { return make_float2(a.x + b.x, a.y + b.y); }
__device__ __forceinline__ float2 csub(float2 a, float2 b) { return make_float2(a.x - b.x, a.y - b.y); }

// In-register DFT-8 (forward, W8 = cis(-2pi/8)), natural order.
__device__ __forceinline__ void dft8(const float2* c, float2* y) {
    const float C = 0.70710678118654752440f;
    float2 s;
    float2 d0 = cadd(c[0], c[4]), d1 = csub(c[0], c[4]);
    float2 d2 = cadd(c[1], c[5]); s = csub(c[1], c[5]);
    float2 d3 = make_float2(C * (s.x + s.y), C * (s.y - s.x));          // * W8^1
    float2 d4 = cadd(c[2], c[6]); s = csub(c[2], c[6]);
    float2 d5 = make_float2(s.y, -s.x);                                  // * -i
    float2 d6 = cadd(c[3], c[7]); s = csub(c[3], c[7]);
    float2 d7 = make_float2(C * (s.y - s.x), -C * (s.x + s.y));          // * W8^3

    float2 e0 = cadd(d0, d4), e2 = csub(d0, d4);
    float2 e1 = cadd(d1, d5), e3 = csub(d1, d5);
    float2 e4 = cadd(d2, d6); s = csub(d2, d6);
    float2 e6 = make_float2(s.y, -s.x);
    float2 e5 = cadd(d3, d7); s = csub(d3, d7);
    float2 e7 = make_float2(s.y, -s.x);

    y[0] = cadd(e0, e4); y[4] = csub(e0, e4);
    y[1] = cadd(e1, e5); y[5] = csub(e1, e5);
    y[2] = cadd(e2, e6); y[6] = csub(e2, e6);
    y[3] = cadd(e3, e7); y[7] = csub(e3, e7);
}

__global__ __launch_bounds__(576, 2)
void imdct_kernel(const float* __restrict__ sig,
                  const float* __restrict__ win,
                  float* __restrict__ out)
{
    // 9 frames x 544 float2. Exchange stages use PAD layout; stage 2 overwrites
    // with inter[] in m-order: float word m = inter[m], m in [0,1024).
    __shared__ float2 fbuf[9][544];

    const int tid = threadIdx.x;
    const int t0  = blockIdx.x * 8;
    const int b   = blockIdx.y;
    const int fid = tid >> 6;
    const int i   = tid & 63;

    // ---- hoist output-stage constants (threads 0..511 only) ----
    // r0 = tid, r1 = tid + 512. Derived closed-form from post/sign (verified R1/R2).
    float wA0, wA1, wB0, wB1;
    int mA0, mA1, mB0, mB1;
    if (tid < 512) {
        const bool odd = (tid & 1) != 0;
        const float inv = 1.0f / 512.0f;
        float w0 = win[tid]        * inv;   // B at r0
        float w1 = win[tid + 512]  * inv;   // B at r1
        float w2 = win[tid + 1024] * inv;   // A at r0
        float w3 = win[tid + 1536] * inv;   // A at r1
        wA0 = odd ? -w2 : w2;               // A,r0: neg iff r0 odd
        wA1 = odd ? w3 : -w3;               // A,r1: neg iff r1 even (== tid even)
        wB0 = odd ? -w0 : w0;               // B: neg iff r odd
        wB1 = odd ? -w1 : w1;
        mA0 = odd ? (511 - tid)  : (513 + tid);
        mA1 = odd ? (1024 - tid) : tid;
        mB0 = odd ? (512 - tid)  : (512 + tid);
        mB1 = odd ? (1023 - tid) : (tid + 1);
    }

    const int gf = t0 + fid;
    const bool valid = gf < 1024;
    const float* sp = sig + ((size_t)(b * 1024 + (valid ? gf : 0))) * 1024;

    // tw[i] = cis(-2pi*(i+0.125)/2048); step per +64 in k: cis(-pi/16)
    float bs, bc;
    __sincosf(-6.283185307179586f * ((float)i + 0.125f) * (1.0f / 2048.0f), &bs, &bc);
    const float2 STEP = make_float2(0.980785280403230449f, -0.195090322016128268f);

    float2 v[8], y[8];

    // ---- load + pre-twiddle: v[r] = (sig[2kk] + i*sig[1023-2kk]) * tw[kk], kk = i + 64r
    {
        float2 tw = make_float2(bc, bs);
        #pragma unroll
        for (int r = 0; r < 8; r++) {
            int kk = i + 64 * r;
            float re = valid ? sp[2 * kk] : 0.0f;
            float im = valid ? sp[1023 - 2 * kk] : 0.0f;
            v[r] = make_float2(re * tw.x - im * tw.y, re * tw.y + im * tw.x);
            tw = cmulf(tw, STEP);
        }
    }

    float2* fb = fbuf[fid];

    // ---- stage 0 (m=1): y = DFT8(v); out[8i + r'] = y[r'] * W512^{i r'}
    dft8(v, y);
    {
        float ws, wc;
        __sincosf(-6.283185307179586f * (float)i * (1.0f / 512.0f), &ws, &wc);
        float2 w1 = make_float2(wc, ws), t = make_float2(1.0f, 0.0f);
        #pragma unroll
        for (int rp = 0; rp < 8; rp++) {
            fb[PAD(8 * i + rp)] = cmulf(y[rp], t);
            t = cmulf(t, w1);
        }
    }
    asm volatile("bar.sync %0, 64;" :: "r"(fid + 1) : "memory");

    // ---- stage 1 (m=8): out[k + 64j + 8r'] = y[r'] * W64^{j r'}
    #pragma unroll
    for (int r = 0; r < 8; r++) v[r] = fb[PAD(i + 64 * r)];
    asm volatile("bar.sync %0, 64;" :: "r"(fid + 1) : "memory");
    dft8(v, y);
    {
        int j = i >> 3, k = i & 7;
        float ws, wc;
        __sincosf(-6.283185307179586f * (float)j * (1.0f / 64.0f), &ws, &wc);
        float2 w1 = make_float2(wc, ws), t = make_float2(1.0f, 0.0f);
        #pragma unroll
        for (int rp = 0; rp < 8; rp++) {
            fb[PAD(k + 64 * j + 8 * rp)] = cmulf(y[rp], t);
            t = cmulf(t, w1);
        }
    }
    asm volatile("bar.sync %0, 64;" :: "r"(fid + 1) : "memory");

    // ---- stage 2 (m=64): X[i + 64r'] = y[r']; fold post-twiddle; store inter[] m-order:
    // inter[2k]=Re X[k], inter[2k+1]=Im X[k] -> float2 store at word 2k (coalesced).
    #pragma unroll
    for (int r = 0; r < 8; r++) v[r] = fb[PAD(i + 64 * r)];
    asm volatile("bar.sync %0, 64;" :: "r"(fid + 1) : "memory");
    dft8(v, y);
    {
        float* fbF = (float*)fb;
        float2 tw = make_float2(bc, bs);
        #pragma unroll
        for (int rp = 0; rp < 8; rp++) {
            int kk = i + 64 * rp;
            *(float2*)&fbF[2 * kk] = cmulf(y[rp], tw);
            tw = cmulf(tw, STEP);
        }
    }
    __syncthreads();

    // ---- output: chunk c -> out[t0+c][r] = inter_c[mA]*wA + inter_{c+1}[mB]*wB
    if (tid < 512) {
        const float* base = (const float*)fbuf;   // frame f at base + f*1088
        float* op = out + (size_t)b * OUTW + (size_t)t0 * 1024 + tid;
        #pragma unroll
        for (int c = 0; c < 8; c++) {
            if (t0 + c > 1022) break;
            const float* f0 = base + c * 1088;
            const float* f1 = base + (c + 1) * 1088;
            op[0]   = f0[mA0] * wA0 + f1[mB0] * wB0;
            op[512] = f0[mA1] * wA1 + f1[mB1] * wB1;
            op += 1024;
        }
    }
}

extern "C" void kernel_launch(void* const* d_in, const int* in_sizes, int n_in,
                              void* d_out, int out_size) {
    const float* sig = (const float*)d_in[0];
    const float* win = (const float*)d_in[1];
    float* out = (float*)d_out;
    dim3 grid(128, 32);
    imdct_kernel<<<grid, 576>>>(sig, win, out);
}

// round 4
// speedup vs baseline: 3.6608x; 1.0061x over previous
#include <cuda_runtime.h>

// FastIMDCT4: B=32, T=1024, n_fft=2048, hop=1024.
// signal: (32, 1024, 1024) f32, window: (2048,) f32
// out: (32, 1, 1, 1047552) f32, y[b, 1024*t + r] = frames[t][1024+r] + frames[t+1][r]
//
// Block: 512 threads = 8 FFT groups x 64 threads -> 7 output chunks.
// 512-pt FFT = 3 in-place DIF radix-8 register stages + 2 padded smem exchanges.
// launch_bounds(512,3) targets 3 resident blocks/SM (reg cap 42).

static constexpr int OUTW = 1023 * 1024;

#define PAD(p) ((p) + ((p) >> 4))

__device__ __forceinline__ float2 cmulf(float2 a, float2 b) {
    return make_float2(a.x * b.x - a.y * b.y, a.x * b.y + a.y * b.x);
}
__device__ __forceinline__ float2 cadd(float2 a, float2 b) { return make_float2(a.x + b.x, a.y + b.y); }
__device__ __forceinline__ float2 csub(float2 a, float2 b) { return make_float2(a.x - b.x, a.y - b.y); }

// In-place DIF radix-8 (W8 = cis(-2pi/8)). Natural-order output X[n] = v[BR[n]],
// BR = {0,4,2,6,1,5,3,7}. Verified by hand on delta, all-ones, e1 inputs.
__device__ __forceinline__ void dft8_ip(float2* v) {
    const float C = 0.70710678118654752440f;
    float2 t;
    // layer 1: pairs stride 4, twiddle W8^k on the difference
    t = csub(v[0], v[4]); v[0] = cadd(v[0], v[4]); v[4] = t;
    t = csub(v[1], v[5]); v[1] = cadd(v[1], v[5]); v[5] = make_float2(C * (t.x + t.y), C * (t.y - t.x));
    t = csub(v[2], v[6]); v[2] = cadd(v[2], v[6]); v[6] = make_float2(t.y, -t.x);
    t = csub(v[3], v[7]); v[3] = cadd(v[3], v[7]); v[7] = make_float2(C * (t.y - t.x), -C * (t.x + t.y));
    // layer 2: pairs stride 2, twiddle W4^k (k=1 -> -i)
    t = csub(v[0], v[2]); v[0] = cadd(v[0], v[2]); v[2] = t;
    t = csub(v[1], v[3]); v[1] = cadd(v[1], v[3]); v[3] = make_float2(t.y, -t.x);
    t = csub(v[4], v[6]); v[4] = cadd(v[4], v[6]); v[6] = t;
    t = csub(v[5], v[7]); v[5] = cadd(v[5], v[7]); v[7] = make_float2(t.y, -t.x);
    // layer 3: pairs stride 1
    t = csub(v[0], v[1]); v[0] = cadd(v[0], v[1]); v[1] = t;
    t = csub(v[2], v[3]); v[2] = cadd(v[2], v[3]); v[3] = t;
    t = csub(v[4], v[5]); v[4] = cadd(v[4], v[5]); v[5] = t;
    t = csub(v[6], v[7]); v[6] = cadd(v[6], v[7]); v[7] = t;
}

__global__ __launch_bounds__(512, 3)
void imdct_kernel(const float* __restrict__ sig,
                  const float* __restrict__ win,
                  float* __restrict__ out)
{
    __shared__ float2 fbuf[8][544];   // 8 frames x (512 + pad); 34.8 KB

    const int tid = threadIdx.x;
    const int t0  = blockIdx.x * 7;
    const int b   = blockIdx.y;
    const int fid = tid >> 6;
    const int i   = tid & 63;

    // compile-time BR + STEP^r = cis(-pi*r/16)
    const int BR[8] = {0, 4, 2, 6, 1, 5, 3, 7};
    const float2 SP[8] = {
        { 1.0f, 0.0f },
        { 0.980785280403230449f, -0.195090322016128268f },
        { 0.923879532511286756f, -0.382683432365089772f },
        { 0.831469612302545237f, -0.555570233019602225f },
        { 0.707106781186547524f, -0.707106781186547524f },
        { 0.555570233019602225f, -0.831469612302545237f },
        { 0.382683432365089772f, -0.923879532511286756f },
        { 0.195090322016128268f, -0.980785280403230449f }
    };

    const int gf = t0 + fid;
    const bool valid = gf < 1024;
    const float2* F = (const float2*)(sig + ((size_t)(b * 1024 + (valid ? gf : 0))) * 1024);

    // base pre/post twiddle: tw(i) = cis(-2pi*(i+0.125)/2048); tw(i+64r) = tw(i)*SP[r]
    float bs, bc;
    __sincosf(-6.283185307179586f * ((float)i + 0.125f) * (1.0f / 2048.0f), &bs, &bc);
    const float2 base = make_float2(bc, bs);

    float2 v[8];

    // ---- load + pre-twiddle: c[kk] = sig[2kk] + i*sig[1023-2kk] = (F[kk].x, F[511-kk].y)
    #pragma unroll
    for (int r = 0; r < 8; r++) {
        int kk = i + 64 * r;
        float re = 0.0f, im = 0.0f;
        if (valid) {
            re = F[kk].x;
            im = F[511 - kk].y;
        }
        float2 tw = cmulf(base, SP[r]);
        v[r] = make_float2(re * tw.x - im * tw.y, re * tw.y + im * tw.x);
    }

    float2* fb = fbuf[fid];

    // ---- stage 0: out[8i + rp] = X[rp] * W512^{i*rp}
    dft8_ip(v);
    {
        float ws, wc;
        __sincosf(-6.283185307179586f * (float)i * (1.0f / 512.0f), &ws, &wc);
        float2 t1 = make_float2(wc, ws);
        float2 t2 = cmulf(t1, t1);
        float2 t3 = cmulf(t1, t2);
        float2 t4 = cmulf(t2, t2);
        fb[PAD(8 * i + 0)] = v[BR[0]];
        fb[PAD(8 * i + 1)] = cmulf(v[BR[1]], t1);
        fb[PAD(8 * i + 2)] = cmulf(v[BR[2]], t2);
        fb[PAD(8 * i + 3)] = cmulf(v[BR[3]], t3);
        fb[PAD(8 * i + 4)] = cmulf(v[BR[4]], t4);
        fb[PAD(8 * i + 5)] = cmulf(v[BR[5]], cmulf(t1, t4));
        fb[PAD(8 * i + 6)] = cmulf(v[BR[6]], cmulf(t2, t4));
        fb[PAD(8 * i + 7)] = cmulf(v[BR[7]], cmulf(t3, t4));
    }
    asm volatile("bar.sync %0, 64;" :: "r"(fid + 1) : "memory");

    // ---- stage 1: out[k + 64j + 8rp] = X[rp] * W64^{j*rp}, i = 8j + k
    #pragma unroll
    for (int r = 0; r < 8; r++) v[r] = fb[PAD(i + 64 * r)];
    asm volatile("bar.sync %0, 64;" :: "r"(fid + 1) : "memory");
    dft8_ip(v);
    {
        const int j = i >> 3, k = i & 7;
        float ws, wc;
        __sincosf(-6.283185307179586f * (float)j * (1.0f / 64.0f), &ws, &wc);
        float2 t1 = make_float2(wc, ws);
        float2 t2 = cmulf(t1, t1);
        float2 t3 = cmulf(t1, t2);
        float2 t4 = cmulf(t2, t2);
        const int o = k + 64 * j;
        fb[PAD(o + 0)]  = v[BR[0]];
        fb[PAD(o + 8)]  = cmulf(v[BR[1]], t1);
        fb[PAD(o + 16)] = cmulf(v[BR[2]], t2);
        fb[PAD(o + 24)] = cmulf(v[BR[3]], t3);
        fb[PAD(o + 32)] = cmulf(v[BR[4]], t4);
        fb[PAD(o + 40)] = cmulf(v[BR[5]], cmulf(t1, t4));
        fb[PAD(o + 48)] = cmulf(v[BR[6]], cmulf(t2, t4));
        fb[PAD(o + 56)] = cmulf(v[BR[7]], cmulf(t3, t4));
    }
    asm volatile("bar.sync %0, 64;" :: "r"(fid + 1) : "memory");

    // ---- stage 2: X[i + 64rp] = v[BR[rp]]; fold post-twiddle tw(i+64rp); store inter[]
    // m-order: float word m = inter[m] (coalesced float2 store at word 2k).
    #pragma unroll
    for (int r = 0; r < 8; r++) v[r] = fb[PAD(i + 64 * r)];
    asm volatile("bar.sync %0, 64;" :: "r"(fid + 1) : "memory");
    dft8_ip(v);
    {
        float* fbF = (float*)fb;
        #pragma unroll
        for (int rp = 0; rp < 8; rp++) {
            float2 tw = cmulf(base, SP[rp]);
            *(float2*)&fbF[2 * (i + 64 * rp)] = cmulf(v[BR[rp]], tw);
        }
    }

    // ---- output constants (computed late to keep live ranges short) ----
    const bool odd = (tid & 1) != 0;
    const float inv = 1.0f / 512.0f;
    float w0 = win[tid]        * inv;   // B at r0
    float w1 = win[tid + 512]  * inv;   // B at r1
    float w2 = win[tid + 1024] * inv;   // A at r0
    float w3 = win[tid + 1536] * inv;   // A at r1
    const float wA0 = odd ? -w2 : w2;
    const float wA1 = odd ?  w3 : -w3;
    const float wB0 = odd ? -w0 : w0;
    const float wB1 = odd ? -w1 : w1;
    const int mA0 = odd ? (511 - tid)  : (513 + tid);
    const int mA1 = odd ? (1024 - tid) : tid;
    const int mB0 = odd ? (512 - tid)  : (512 + tid);
    const int mB1 = odd ? (1023 - tid) : (tid + 1);

    __syncthreads();

    // ---- output: chunk c -> out[t0+c][r] = inter_c[mA]*wA + inter_{c+1}[mB]*wB
    {
        const float* bse = (const float*)fbuf;   // frame f at bse + f*1088
        float* op = out + (size_t)b * OUTW + (size_t)t0 * 1024 + tid;
        #pragma unroll
        for (int c = 0; c < 7; c++) {
            if (t0 + c > 1022) break;
            const float* f0 = bse + c * 1088;
            const float* f1 = bse + (c + 1) * 1088;
            op[0]   = f0[mA0] * wA0 + f1[mB0] * wB0;
            op[512] = f0[mA1] * wA1 + f1[mB1] * wB1;
            op += 1024;
        }
    }
}

extern "C" void kernel_launch(void* const* d_in, const int* in_sizes, int n_in,
                              void* d_out, int out_size) {
    const float* sig = (const float*)d_in[0];
    const float* win = (const float*)d_in[1];
    float* out = (float*)d_out;
    dim3 grid(147, 32);   // 147*7 = 1029 >= 1023 chunks
    imdct_kernel<<<grid, 512>>>(sig, win, out);
}

// round 5
// speedup vs baseline: 3.8104x; 1.0409x over previous
#include <cuda_runtime.h>

// FastIMDCT4: B=32, T=1024, n_fft=2048, hop=1024.
// signal: (32, 1024, 1024) f32, window: (2048,) f32
// out: (32, 1, 1, 1047552) f32, y[b, 1024*t + r] = frames[t][1024+r] + frames[t+1][r]
//
// Block: 512 threads = 8 FFT groups x 64 threads -> 7 output chunks.
// 512-pt FFT = 3 in-place DIF radix-8 register stages + 2 XOR-swizzled,
// bank-conflict-free smem exchanges (no padding).

static constexpr int OUTW = 1023 * 1024;

__device__ __forceinline__ float2 cmulf(float2 a, float2 b) {
    return make_float2(a.x * b.x - a.y * b.y, a.x * b.y + a.y * b.x);
}
__device__ __forceinline__ float2 cadd(float2 a, float2 b) { return make_float2(a.x + b.x, a.y + b.y); }
__device__ __forceinline__ float2 csub(float2 a, float2 b) { return make_float2(a.x - b.x, a.y - b.y); }

// In-place DIF radix-8 (W8 = cis(-2pi/8)). Natural-order output X[n] = v[BR[n]],
// BR = {0,4,2,6,1,5,3,7}.
__device__ __forceinline__ void dft8_ip(float2* v) {
    const float C = 0.70710678118654752440f;
    float2 t;
    t = csub(v[0], v[4]); v[0] = cadd(v[0], v[4]); v[4] = t;
    t = csub(v[1], v[5]); v[1] = cadd(v[1], v[5]); v[5] = make_float2(C * (t.x + t.y), C * (t.y - t.x));
    t = csub(v[2], v[6]); v[2] = cadd(v[2], v[6]); v[6] = make_float2(t.y, -t.x);
    t = csub(v[3], v[7]); v[3] = cadd(v[3], v[7]); v[7] = make_float2(C * (t.y - t.x), -C * (t.x + t.y));
    t = csub(v[0], v[2]); v[0] = cadd(v[0], v[2]); v[2] = t;
    t = csub(v[1], v[3]); v[1] = cadd(v[1], v[3]); v[3] = make_float2(t.y, -t.x);
    t = csub(v[4], v[6]); v[4] = cadd(v[4], v[6]); v[6] = t;
    t = csub(v[5], v[7]); v[5] = cadd(v[5], v[7]); v[7] = make_float2(t.y, -t.x);
    t = csub(v[0], v[1]); v[0] = cadd(v[0], v[1]); v[1] = t;
    t = csub(v[2], v[3]); v[2] = cadd(v[2], v[3]); v[3] = t;
    t = csub(v[4], v[5]); v[4] = cadd(v[4], v[5]); v[5] = t;
    t = csub(v[6], v[7]); v[6] = cadd(v[6], v[7]); v[7] = t;
}

__global__ __launch_bounds__(512, 3)
void imdct_kernel(const float* __restrict__ sig,
                  const float* __restrict__ win,
                  float* __restrict__ out)
{
    __shared__ float2 fbuf[8][512];   // 32 KB; exchange + final inter[] per frame

    const int tid = threadIdx.x;
    const int t0  = blockIdx.x * 7;
    const int b   = blockIdx.y;
    const int fid = tid >> 6;
    const int i   = tid & 63;

    const int BR[8] = {0, 4, 2, 6, 1, 5, 3, 7};
    const float2 SP[8] = {
        { 1.0f, 0.0f },
        { 0.980785280403230449f, -0.195090322016128268f },
        { 0.923879532511286756f, -0.382683432365089772f },
        { 0.831469612302545237f, -0.555570233019602225f },
        { 0.707106781186547524f, -0.707106781186547524f },
        { 0.555570233019602225f, -0.831469612302545237f },
        { 0.382683432365089772f, -0.923879532511286756f },
        { 0.195090322016128268f, -0.980785280403230449f }
    };

    const int gf = t0 + fid;
    const bool valid = gf < 1024;
    const float2* F = (const float2*)(sig + ((size_t)(b * 1024 + (valid ? gf : 0))) * 1024);

    // swizzle constants
    // S1(p) = p ^ (b6 | b4<<1 | b5<<2):
    //   writer (p = 8i+rp):  x = (i>>3&1) | (i>>1&1)<<1 | (i>>2&1)<<2  (thread-const)
    //   reader (p = i+64r):  x = (r&1) | (i>>4&1)<<1 | (i>>5&1)<<2
    const int xw  = ((i >> 3) & 1) | (((i >> 1) & 1) << 1) | (((i >> 2) & 1) << 2);
    const int xr0 = (((i >> 4) & 1) << 1) | (((i >> 5) & 1) << 2);

    // pre/post twiddle: tw(i) = cis(-2pi*(i+0.125)/2048); tw(i+64r) = tw(i)*SP[r]
    float bs, bc;
    __sincosf(-6.283185307179586f * ((float)i + 0.125f) * (1.0f / 2048.0f), &bs, &bc);
    const float2 base = make_float2(bc, bs);

    float2 v[8];

    // ---- load + pre-twiddle: c[kk] = (F[kk].x, F[511-kk].y), kk = i + 64r
    #pragma unroll
    for (int r = 0; r < 8; r++) {
        int kk = i + 64 * r;
        float re = 0.0f, im = 0.0f;
        if (valid) {
            re = F[kk].x;
            im = F[511 - kk].y;
        }
        float2 tw = cmulf(base, SP[r]);
        v[r] = make_float2(re * tw.x - im * tw.y, re * tw.y + im * tw.x);
    }

    float2* fb = fbuf[fid];

    // ---- stage 0: logical fb[8i + rp] = X[rp] * W512^{i*rp}, stored at S1
    dft8_ip(v);
    {
        float ws, wc;
        __sincosf(-6.283185307179586f * (float)i * (1.0f / 512.0f), &ws, &wc);
        float2 t1 = make_float2(wc, ws);
        float2 t2 = cmulf(t1, t1);
        float2 t3 = cmulf(t1, t2);
        float2 t4 = cmulf(t2, t2);
        const int bse = 8 * i;
        fb[bse + (0 ^ xw)] = v[BR[0]];
        fb[bse + (1 ^ xw)] = cmulf(v[BR[1]], t1);
        fb[bse + (2 ^ xw)] = cmulf(v[BR[2]], t2);
        fb[bse + (3 ^ xw)] = cmulf(v[BR[3]], t3);
        fb[bse + (4 ^ xw)] = cmulf(v[BR[4]], t4);
        fb[bse + (5 ^ xw)] = cmulf(v[BR[5]], cmulf(t1, t4));
        fb[bse + (6 ^ xw)] = cmulf(v[BR[6]], cmulf(t2, t4));
        fb[bse + (7 ^ xw)] = cmulf(v[BR[7]], cmulf(t3, t4));
    }
    asm volatile("bar.sync %0, 64;" :: "r"(fid + 1) : "memory");

    // ---- stage 1: load logical i+64r via S1; write logical o+8rp via S2
    #pragma unroll
    for (int r = 0; r < 8; r++)
        v[r] = fb[(i ^ xr0 ^ (r & 1)) + 64 * r];
    asm volatile("bar.sync %0, 64;" :: "r"(fid + 1) : "memory");
    dft8_ip(v);
    {
        const int j = i >> 3, k = i & 7;
        const int jb = (j & 1);
        float ws, wc;
        __sincosf(-6.283185307179586f * (float)j * (1.0f / 64.0f), &ws, &wc);
        float2 t1 = make_float2(wc, ws);
        float2 t2 = cmulf(t1, t1);
        float2 t3 = cmulf(t1, t2);
        float2 t4 = cmulf(t2, t2);
        const int o = k + 64 * j;
        // S2(q) = q ^ 8*b6(q); b6(q) = j&1 here -> slot rp^jb
        fb[o + 8 * (0 ^ jb)] = v[BR[0]];
        fb[o + 8 * (1 ^ jb)] = cmulf(v[BR[1]], t1);
        fb[o + 8 * (2 ^ jb)] = cmulf(v[BR[2]], t2);
        fb[o + 8 * (3 ^ jb)] = cmulf(v[BR[3]], t3);
        fb[o + 8 * (4 ^ jb)] = cmulf(v[BR[4]], t4);
        fb[o + 8 * (5 ^ jb)] = cmulf(v[BR[5]], cmulf(t1, t4));
        fb[o + 8 * (6 ^ jb)] = cmulf(v[BR[6]], cmulf(t2, t4));
        fb[o + 8 * (7 ^ jb)] = cmulf(v[BR[7]], cmulf(t3, t4));
    }
    asm volatile("bar.sync %0, 64;" :: "r"(fid + 1) : "memory");

    // ---- stage 2: load logical i+64r via S2; fold post-twiddle; store inter[] m-order
    #pragma unroll
    for (int r = 0; r < 8; r++)
        v[r] = fb[(i ^ (8 * (r & 1))) + 64 * r];
    asm volatile("bar.sync %0, 64;" :: "r"(fid + 1) : "memory");
    dft8_ip(v);
    {
        float* fbF = (float*)fb;
        #pragma unroll
        for (int rp = 0; rp < 8; rp++) {
            float2 tw = cmulf(base, SP[rp]);
            *(float2*)&fbF[2 * (i + 64 * rp)] = cmulf(v[BR[rp]], tw);
        }
    }

    // ---- output constants (late, short live ranges) ----
    const bool odd = (tid & 1) != 0;
    const float inv = 1.0f / 512.0f;
    float w0 = win[tid]        * inv;
    float w1 = win[tid + 512]  * inv;
    float w2 = win[tid + 1024] * inv;
    float w3 = win[tid + 1536] * inv;
    const float wA0 = odd ? -w2 : w2;
    const float wA1 = odd ?  w3 : -w3;
    const float wB0 = odd ? -w0 : w0;
    const float wB1 = odd ? -w1 : w1;
    const int mA0 = odd ? (511 - tid)  : (513 + tid);
    const int mA1 = odd ? (1024 - tid) : tid;
    const int mB0 = odd ? (512 - tid)  : (512 + tid);
    const int mB1 = odd ? (1023 - tid) : (tid + 1);

    __syncthreads();

    // ---- output: chunk c -> out[t0+c][r] = inter_c[mA]*wA + inter_{c+1}[mB]*wB
    {
        const float* bse = (const float*)fbuf;   // frame f at bse + f*1024
        float* op = out + (size_t)b * OUTW + (size_t)t0 * 1024 + tid;
        #pragma unroll
        for (int c = 0; c < 7; c++) {
            if (t0 + c > 1022) break;
            const float* f0 = bse + c * 1024;
            const float* f1 = bse + (c + 1) * 1024;
            op[0]   = f0[mA0] * wA0 + f1[mB0] * wB0;
            op[512] = f0[mA1] * wA1 + f1[mB1] * wB1;
            op += 1024;
        }
    }
}

extern "C" void kernel_launch(void* const* d_in, const int* in_sizes, int n_in,
                              void* d_out, int out_size) {
    const float* sig = (const float*)d_in[0];
    const float* win = (const float*)d_in[1];
    float* out = (float*)d_out;
    dim3 grid(147, 32);   // 147*7 = 1029 >= 1023 chunks
    imdct_kernel<<<grid, 512>>>(sig, win, out);
}

// round 6
// speedup vs baseline: 3.9995x; 1.0496x over previous
#include <cuda_runtime.h>

// FastIMDCT4: B=32, T=1024, n_fft=2048, hop=1024.
// signal: (32, 1024, 1024) f32, window: (2048,) f32
// out: (32, 1, 1, 1047552) f32, y[b, 1024*t + r] = frames[t][1024+r] + frames[t+1][r]
//
// Block: 512 threads = 8 FFT groups x 64 threads -> 7 output chunks.
// 512-pt FFT = 3 in-place DIF radix-8 stages with packed f32x2 butterflies,
// 2 XOR-swizzled conflict-free smem exchanges. Lane remap puts mirror partner
// (63-i) in the same warp so input loads are full-width (shfl for imag parts).

static constexpr int OUTW = 1023 * 1024;

using u64 = unsigned long long;

__device__ __forceinline__ u64 pack2(float x, float y) {
    u64 r; asm("mov.b64 %0,{%1,%2};" : "=l"(r) : "f"(x), "f"(y)); return r;
}
__device__ __forceinline__ float2 unpack2(u64 a) {
    float2 f; asm("mov.b64 {%0,%1},%2;" : "=f"(f.x), "=f"(f.y) : "l"(a)); return f;
}
__device__ __forceinline__ u64 padd(u64 a, u64 b) {
    u64 r; asm("add.rn.f32x2 %0,%1,%2;" : "=l"(r) : "l"(a), "l"(b)); return r;
}
__device__ __forceinline__ u64 pmul(u64 a, u64 b) {
    u64 r; asm("mul.rn.f32x2 %0,%1,%2;" : "=l"(r) : "l"(a), "l"(b)); return r;
}
__device__ __forceinline__ u64 pfma(u64 a, u64 b, u64 c) {
    u64 r; asm("fma.rn.f32x2 %0,%1,%2,%3;" : "=l"(r) : "l"(a), "l"(b), "l"(c)); return r;
}

__device__ __forceinline__ float2 cmulf(float2 a, float2 b) {
    return make_float2(a.x * b.x - a.y * b.y, a.x * b.y + a.y * b.x);
}
// packed value * float2 twiddle
__device__ __forceinline__ u64 cmul_pk(u64 a, float2 b) {
    float2 s = unpack2(a);
    return pack2(s.x * b.x - s.y * b.y, s.x * b.y + s.y * b.x);
}

// In-place DIF radix-8, packed lanes (lo=Re, hi=Im). X[n] = v[BR[n]],
// BR = {0,4,2,6,1,5,3,7}. Same structure as the verified scalar dft8_ip.
__device__ __forceinline__ void dft8_pk(u64* v) {
    const u64 M1 = 0xBF800000BF800000ULL;   // (-1,-1)
    const u64 CC = 0x3F3504F33F3504F3ULL;   // (C,C), C = 1/sqrt(2)
    u64 t; float2 s;
    // layer 1 (stride 4, W8^k on the difference)
    t = pfma(v[4], M1, v[0]); v[0] = padd(v[0], v[4]); v[4] = t;
    t = pfma(v[5], M1, v[1]); v[1] = padd(v[1], v[5]);
    s = unpack2(t); v[5] = pmul(pack2(s.x + s.y, s.y - s.x), CC);       // * W8^1
    t = pfma(v[6], M1, v[2]); v[2] = padd(v[2], v[6]);
    s = unpack2(t); v[6] = pack2(s.y, -s.x);                            // * -i
    t = pfma(v[7], M1, v[3]); v[3] = padd(v[3], v[7]);
    s = unpack2(t); v[7] = pmul(pack2(s.y - s.x, -s.x - s.y), CC);      // * W8^3
    // layer 2 (stride 2, -i on odd pair)
    t = pfma(v[2], M1, v[0]); v[0] = padd(v[0], v[2]); v[2] = t;
    t = pfma(v[3], M1, v[1]); v[1] = padd(v[1], v[3]);
    s = unpack2(t); v[3] = pack2(s.y, -s.x);
    t = pfma(v[6], M1, v[4]); v[4] = padd(v[4], v[6]); v[6] = t;
    t = pfma(v[7], M1, v[5]); v[5] = padd(v[5], v[7]);
    s = unpack2(t); v[7] = pack2(s.y, -s.x);
    // layer 3 (stride 1)
    t = pfma(v[1], M1, v[0]); v[0] = padd(v[0], v[1]); v[1] = t;
    t = pfma(v[3], M1, v[2]); v[2] = padd(v[2], v[3]); v[3] = t;
    t = pfma(v[5], M1, v[4]); v[4] = padd(v[4], v[5]); v[5] = t;
    t = pfma(v[7], M1, v[6]); v[6] = padd(v[6], v[7]); v[7] = t;
}

__global__ __launch_bounds__(512, 3)
void imdct_kernel(const float* __restrict__ sig,
                  const float* __restrict__ win,
                  float* __restrict__ out)
{
    __shared__ float2 fbuf[8][512];   // 32 KB

    const int tid = threadIdx.x;
    const int t0  = blockIdx.x * 7;
    const int b   = blockIdx.y;
    const int fid = tid >> 6;
    const int u   = tid & 63;

    // lane remap: warpA holds i in {0..15, 48..63}, warpB holds {16..47};
    // each 16-lane LDS phase is 16 consecutive, 16-aligned i values, and the
    // mirror partner 63-i is at lane^16 within the same warp.
    const int q = u >> 4;
    const int i = (q == 0) ? u : (q == 1) ? (79 - u) : (q == 2) ? (u - 16) : (95 - u);

    const int BR[8] = {0, 4, 2, 6, 1, 5, 3, 7};
    const float2 SP[8] = {
        { 1.0f, 0.0f },
        { 0.980785280403230449f, -0.195090322016128268f },
        { 0.923879532511286756f, -0.382683432365089772f },
        { 0.831469612302545237f, -0.555570233019602225f },
        { 0.707106781186547524f, -0.707106781186547524f },
        { 0.555570233019602225f, -0.831469612302545237f },
        { 0.382683432365089772f, -0.923879532511286756f },
        { 0.195090322016128268f, -0.980785280403230449f }
    };

    const int gf = t0 + fid;
    const bool valid = gf < 1024;
    const float2* F = (const float2*)(sig + ((size_t)(b * 1024 + (valid ? gf : 0))) * 1024);

    // swizzle constants (same S1/S2 as verified round 5, indexed by i)
    const int xw  = ((i >> 3) & 1) | (((i >> 1) & 1) << 1) | (((i >> 2) & 1) << 2);
    const int xr0 = (((i >> 4) & 1) << 1) | (((i >> 5) & 1) << 2);

    // pre/post twiddle: tw(i) = cis(-2pi*(i+0.125)/2048); tw(i+64r) = tw(i)*SP[r]
    float bs, bc;
    __sincosf(-6.283185307179586f * ((float)i + 0.125f) * (1.0f / 2048.0f), &bs, &bc);
    const float2 base = make_float2(bc, bs);

    u64 v[8];

    // ---- load + pre-twiddle in mirror pairs (r, 7-r):
    // re(kk) = F[kk].x from own load; im(kk) = F[511-kk].y = partner's load .y
    #pragma unroll
    for (int rp = 0; rp < 4; rp++) {
        float2 ga = valid ? F[i + 64 * rp]       : make_float2(0.f, 0.f);
        float2 gb = valid ? F[i + 64 * (7 - rp)] : make_float2(0.f, 0.f);
        float ima = __shfl_xor_sync(0xffffffffu, gb.y, 16);
        float imb = __shfl_xor_sync(0xffffffffu, ga.y, 16);
        float2 ta = cmulf(base, SP[rp]);
        float2 tb = cmulf(base, SP[7 - rp]);
        v[rp]     = pack2(ga.x * ta.x - ima * ta.y, ga.x * ta.y + ima * ta.x);
        v[7 - rp] = pack2(gb.x * tb.x - imb * tb.y, gb.x * tb.y + imb * tb.x);
    }

    float2* fb = fbuf[fid];

    // ---- stage 0: logical fb[8i + rp] = X[rp] * W512^{i*rp}, stored at S1
    dft8_pk(v);
    {
        float ws, wc;
        __sincosf(-6.283185307179586f * (float)i * (1.0f / 512.0f), &ws, &wc);
        float2 t1 = make_float2(wc, ws);
        float2 t2 = cmulf(t1, t1);
        float2 t3 = cmulf(t1, t2);
        float2 t4 = cmulf(t2, t2);
        const int bse = 8 * i;
        u64* fbq = (u64*)fb;
        fbq[bse + (0 ^ xw)] = v[BR[0]];
        fbq[bse + (1 ^ xw)] = cmul_pk(v[BR[1]], t1);
        fbq[bse + (2 ^ xw)] = cmul_pk(v[BR[2]], t2);
        fbq[bse + (3 ^ xw)] = cmul_pk(v[BR[3]], t3);
        fbq[bse + (4 ^ xw)] = cmul_pk(v[BR[4]], t4);
        fbq[bse + (5 ^ xw)] = cmul_pk(v[BR[5]], cmulf(t1, t4));
        fbq[bse + (6 ^ xw)] = cmul_pk(v[BR[6]], cmulf(t2, t4));
        fbq[bse + (7 ^ xw)] = cmul_pk(v[BR[7]], cmulf(t3, t4));
    }
    asm volatile("bar.sync %0, 64;" :: "r"(fid + 1) : "memory");

    // ---- stage 1: load logical i+64r via S1; write logical o+8rp via S2
    {
        const u64* fbq = (const u64*)fb;
        #pragma unroll
        for (int r = 0; r < 8; r++)
            v[r] = fbq[(i ^ xr0 ^ (r & 1)) + 64 * r];
    }
    asm volatile("bar.sync %0, 64;" :: "r"(fid + 1) : "memory");
    dft8_pk(v);
    {
        const int j = i >> 3, k = i & 7;
        const int jb = (j & 1);
        float ws, wc;
        __sincosf(-6.283185307179586f * (float)j * (1.0f / 64.0f), &ws, &wc);
        float2 t1 = make_float2(wc, ws);
        float2 t2 = cmulf(t1, t1);
        float2 t3 = cmulf(t1, t2);
        float2 t4 = cmulf(t2, t2);
        const int o = k + 64 * j;
        u64* fbq = (u64*)fb;
        fbq[o + 8 * (0 ^ jb)] = v[BR[0]];
        fbq[o + 8 * (1 ^ jb)] = cmul_pk(v[BR[1]], t1);
        fbq[o + 8 * (2 ^ jb)] = cmul_pk(v[BR[2]], t2);
        fbq[o + 8 * (3 ^ jb)] = cmul_pk(v[BR[3]], t3);
        fbq[o + 8 * (4 ^ jb)] = cmul_pk(v[BR[4]], t4);
        fbq[o + 8 * (5 ^ jb)] = cmul_pk(v[BR[5]], cmulf(t1, t4));
        fbq[o + 8 * (6 ^ jb)] = cmul_pk(v[BR[6]], cmulf(t2, t4));
        fbq[o + 8 * (7 ^ jb)] = cmul_pk(v[BR[7]], cmulf(t3, t4));
    }
    asm volatile("bar.sync %0, 64;" :: "r"(fid + 1) : "memory");

    // ---- stage 2: load logical i+64r via S2; post-twiddle; store inter[] m-order
    {
        const u64* fbq = (const u64*)fb;
        #pragma unroll
        for (int r = 0; r < 8; r++)
            v[r] = fbq[(i ^ (8 * (r & 1))) + 64 * r];
    }
    asm volatile("bar.sync %0, 64;" :: "r"(fid + 1) : "memory");
    dft8_pk(v);
    {
        u64* fbq = (u64*)fb;
        #pragma unroll
        for (int rp = 0; rp < 8; rp++) {
            float2 tw = cmulf(base, SP[rp]);
            fbq[i + 64 * rp] = cmul_pk(v[BR[rp]], tw);
        }
    }

    // ---- output constants (late, short live ranges) ----
    const bool odd = (tid & 1) != 0;
    const float inv = 1.0f / 512.0f;
    float w0 = win[tid]        * inv;
    float w1 = win[tid + 512]  * inv;
    float w2 = win[tid + 1024] * inv;
    float w3 = win[tid + 1536] * inv;
    const float wA0 = odd ? -w2 : w2;
    const float wA1 = odd ?  w3 : -w3;
    const float wB0 = odd ? -w0 : w0;
    const float wB1 = odd ? -w1 : w1;
    const int mA0 = odd ? (511 - tid)  : (513 + tid);
    const int mA1 = odd ? (1024 - tid) : tid;
    const int mB0 = odd ? (512 - tid)  : (512 + tid);
    const int mB1 = odd ? (1023 - tid) : (tid + 1);

    __syncthreads();

    // ---- output: chunk c -> out[t0+c][r] = inter_c[mA]*wA + inter_{c+1}[mB]*wB
    {
        const float* bse = (const float*)fbuf;   // frame f at bse + f*1024
        float* op = out + (size_t)b * OUTW + (size_t)t0 * 1024 + tid;
        #pragma unroll
        for (int c = 0; c < 7; c++) {
            if (t0 + c > 1022) break;
            const float* f0 = bse + c * 1024;
            const float* f1 = bse + (c + 1) * 1024;
            op[0]   = f0[mA0] * wA0 + f1[mB0] * wB0;
            op[512] = f0[mA1] * wA1 + f1[mB1] * wB1;
            op += 1024;
        }
    }
}

extern "C" void kernel_launch(void* const* d_in, const int* in_sizes, int n_in,
                              void* d_out, int out_size) {
    const float* sig = (const float*)d_in[0];
    const float* win = (const float*)d_in[1];
    float* out = (float*)d_out;
    dim3 grid(147, 32);   // 147*7 = 1029 >= 1023 chunks
    imdct_kernel<<<grid, 512>>>(sig, win, out);
}

// round 7
// speedup vs baseline: 4.1187x; 1.0298x over previous
#include <cuda_runtime.h>

// FastIMDCT4: B=32, T=1024, n_fft=2048, hop=1024.
// signal: (32, 1024, 1024) f32, window: (2048,) f32
// out: (32, 1, 1, 1047552) f32, y[b, 1024*t + r] = frames[t][1024+r] + frames[t+1][r]
//
// Block: 512 threads = 8 FFT groups x 64 threads -> 7 output chunks.
// 512-pt FFT = 3 in-place DIF radix-8 stages with packed f32x2 butterflies,
// 2 XOR-swizzled conflict-free smem exchanges. launch_bounds(512,4) targets
// 4 resident blocks/SM (32-reg cap); long-lived registers minimized (base
// twiddle recomputed in stage 2 instead of carried).

static constexpr int OUTW = 1023 * 1024;

using u64 = unsigned long long;

__device__ __forceinline__ u64 pack2(float x, float y) {
    u64 r; asm("mov.b64 %0,{%1,%2};" : "=l"(r) : "f"(x), "f"(y)); return r;
}
__device__ __forceinline__ float2 unpack2(u64 a) {
    float2 f; asm("mov.b64 {%0,%1},%2;" : "=f"(f.x), "=f"(f.y) : "l"(a)); return f;
}
__device__ __forceinline__ u64 padd(u64 a, u64 b) {
    u64 r; asm("add.rn.f32x2 %0,%1,%2;" : "=l"(r) : "l"(a), "l"(b)); return r;
}
__device__ __forceinline__ u64 pmul(u64 a, u64 b) {
    u64 r; asm("mul.rn.f32x2 %0,%1,%2;" : "=l"(r) : "l"(a), "l"(b)); return r;
}
__device__ __forceinline__ u64 pfma(u64 a, u64 b, u64 c) {
    u64 r; asm("fma.rn.f32x2 %0,%1,%2,%3;" : "=l"(r) : "l"(a), "l"(b), "l"(c)); return r;
}

__device__ __forceinline__ float2 cmulf(float2 a, float2 b) {
    return make_float2(a.x * b.x - a.y * b.y, a.x * b.y + a.y * b.x);
}
// packed value * float2 twiddle
__device__ __forceinline__ u64 cmul_pk(u64 a, float2 b) {
    float2 s = unpack2(a);
    return pack2(s.x * b.x - s.y * b.y, s.x * b.y + s.y * b.x);
}

// In-place DIF radix-8, packed lanes (lo=Re, hi=Im). X[n] = v[BR[n]],
// BR = {0,4,2,6,1,5,3,7}.
__device__ __forceinline__ void dft8_pk(u64* v) {
    const u64 M1 = 0xBF800000BF800000ULL;   // (-1,-1)
    const u64 CC = 0x3F3504F33F3504F3ULL;   // (C,C), C = 1/sqrt(2)
    u64 t; float2 s;
    t = pfma(v[4], M1, v[0]); v[0] = padd(v[0], v[4]); v[4] = t;
    t = pfma(v[5], M1, v[1]); v[1] = padd(v[1], v[5]);
    s = unpack2(t); v[5] = pmul(pack2(s.x + s.y, s.y - s.x), CC);       // * W8^1
    t = pfma(v[6], M1, v[2]); v[2] = padd(v[2], v[6]);
    s = unpack2(t); v[6] = pack2(s.y, -s.x);                            // * -i
    t = pfma(v[7], M1, v[3]); v[3] = padd(v[3], v[7]);
    s = unpack2(t); v[7] = pmul(pack2(s.y - s.x, -s.x - s.y), CC);      // * W8^3
    t = pfma(v[2], M1, v[0]); v[0] = padd(v[0], v[2]); v[2] = t;
    t = pfma(v[3], M1, v[1]); v[1] = padd(v[1], v[3]);
    s = unpack2(t); v[3] = pack2(s.y, -s.x);
    t = pfma(v[6], M1, v[4]); v[4] = padd(v[4], v[6]); v[6] = t;
    t = pfma(v[7], M1, v[5]); v[5] = padd(v[5], v[7]);
    s = unpack2(t); v[7] = pack2(s.y, -s.x);
    t = pfma(v[1], M1, v[0]); v[0] = padd(v[0], v[1]); v[1] = t;
    t = pfma(v[3], M1, v[2]); v[2] = padd(v[2], v[3]); v[3] = t;
    t = pfma(v[5], M1, v[4]); v[4] = padd(v[4], v[5]); v[5] = t;
    t = pfma(v[7], M1, v[6]); v[6] = padd(v[6], v[7]); v[7] = t;
}

__global__ __launch_bounds__(512, 4)
void imdct_kernel(const float* __restrict__ sig,
                  const float* __restrict__ win,
                  float* __restrict__ out)
{
    __shared__ float2 fbuf[8][512];   // 32 KB

    const int tid = threadIdx.x;
    const int t0  = blockIdx.x * 7;
    const int b   = blockIdx.y;
    const int fid = tid >> 6;

    // lane remap: each 16-lane LDS phase is 16 consecutive, 16-aligned i values;
    // mirror partner 63-i sits at lane^16 within the same warp.
    const int u = tid & 63;
    const int q = u >> 4;
    const int i = (q == 0) ? u : (q == 1) ? (79 - u) : (q == 2) ? (u - 16) : (95 - u);

    const int BR[8] = {0, 4, 2, 6, 1, 5, 3, 7};
    const float2 SP[8] = {
        { 1.0f, 0.0f },
        { 0.980785280403230449f, -0.195090322016128268f },
        { 0.923879532511286756f, -0.382683432365089772f },
        { 0.831469612302545237f, -0.555570233019602225f },
        { 0.707106781186547524f, -0.707106781186547524f },
        { 0.555570233019602225f, -0.831469612302545237f },
        { 0.382683432365089772f, -0.923879532511286756f },
        { 0.195090322016128268f, -0.980785280403230449f }
    };

    u64 v[8];

    // ---- load + pre-twiddle in mirror pairs (r, 7-r):
    // re(kk) = F[kk].x; im(kk) = F[511-kk].y via partner lane (^16)
    {
        const int gf = t0 + fid;
        const bool valid = gf < 1024;
        const float2* F = (const float2*)(sig + ((size_t)(b * 1024 + (valid ? gf : 0))) * 1024);
        float bs, bc;
        __sincosf(-6.283185307179586f * ((float)i + 0.125f) * (1.0f / 2048.0f), &bs, &bc);
        const float2 base = make_float2(bc, bs);
        #pragma unroll
        for (int rp = 0; rp < 4; rp++) {
            float2 ga = valid ? F[i + 64 * rp]       : make_float2(0.f, 0.f);
            float2 gb = valid ? F[i + 64 * (7 - rp)] : make_float2(0.f, 0.f);
            float ima = __shfl_xor_sync(0xffffffffu, gb.y, 16);
            float imb = __shfl_xor_sync(0xffffffffu, ga.y, 16);
            float2 ta = cmulf(base, SP[rp]);
            float2 tb = cmulf(base, SP[7 - rp]);
            v[rp]     = pack2(ga.x * ta.x - ima * ta.y, ga.x * ta.y + ima * ta.x);
            v[7 - rp] = pack2(gb.x * tb.x - imb * tb.y, gb.x * tb.y + imb * tb.x);
        }
    }

    float2* fb = fbuf[fid];

    // ---- stage 0: logical fb[8i + rp] = X[rp] * W512^{i*rp}, stored at S1
    dft8_pk(v);
    {
        const int xw = ((i >> 3) & 1) | (((i >> 1) & 1) << 1) | (((i >> 2) & 1) << 2);
        float ws, wc;
        __sincosf(-6.283185307179586f * (float)i * (1.0f / 512.0f), &ws, &wc);
        float2 t1 = make_float2(wc, ws);
        float2 t2 = cmulf(t1, t1);
        float2 t3 = cmulf(t1, t2);
        float2 t4 = cmulf(t2, t2);
        const int bse = 8 * i;
        u64* fbq = (u64*)fb;
        fbq[bse + (0 ^ xw)] = v[BR[0]];
        fbq[bse + (1 ^ xw)] = cmul_pk(v[BR[1]], t1);
        fbq[bse + (2 ^ xw)] = cmul_pk(v[BR[2]], t2);
        fbq[bse + (3 ^ xw)] = cmul_pk(v[BR[3]], t3);
        fbq[bse + (4 ^ xw)] = cmul_pk(v[BR[4]], t4);
        fbq[bse + (5 ^ xw)] = cmul_pk(v[BR[5]], cmulf(t1, t4));
        fbq[bse + (6 ^ xw)] = cmul_pk(v[BR[6]], cmulf(t2, t4));
        fbq[bse + (7 ^ xw)] = cmul_pk(v[BR[7]], cmulf(t3, t4));
    }
    asm volatile("bar.sync %0, 64;" :: "r"(fid + 1) : "memory");

    // ---- stage 1: load logical i+64r via S1; write logical o+8rp via S2
    {
        const int xr0 = (((i >> 4) & 1) << 1) | (((i >> 5) & 1) << 2);
        const u64* fbq = (const u64*)fb;
        #pragma unroll
        for (int r = 0; r < 8; r++)
            v[r] = fbq[(i ^ xr0 ^ (r & 1)) + 64 * r];
    }
    asm volatile("bar.sync %0, 64;" :: "r"(fid + 1) : "memory");
    dft8_pk(v);
    {
        const int j = i >> 3, k = i & 7;
        const int jb = (j & 1);
        float ws, wc;
        __sincosf(-6.283185307179586f * (float)j * (1.0f / 64.0f), &ws, &wc);
        float2 t1 = make_float2(wc, ws);
        float2 t2 = cmulf(t1, t1);
        float2 t3 = cmulf(t1, t2);
        float2 t4 = cmulf(t2, t2);
        const int o = k + 64 * j;
        u64* fbq = (u64*)fb;
        fbq[o + 8 * (0 ^ jb)] = v[BR[0]];
        fbq[o + 8 * (1 ^ jb)] = cmul_pk(v[BR[1]], t1);
        fbq[o + 8 * (2 ^ jb)] = cmul_pk(v[BR[2]], t2);
        fbq[o + 8 * (3 ^ jb)] = cmul_pk(v[BR[3]], t3);
        fbq[o + 8 * (4 ^ jb)] = cmul_pk(v[BR[4]], t4);
        fbq[o + 8 * (5 ^ jb)] = cmul_pk(v[BR[5]], cmulf(t1, t4));
        fbq[o + 8 * (6 ^ jb)] = cmul_pk(v[BR[6]], cmulf(t2, t4));
        fbq[o + 8 * (7 ^ jb)] = cmul_pk(v[BR[7]], cmulf(t3, t4));
    }
    asm volatile("bar.sync %0, 64;" :: "r"(fid + 1) : "memory");

    // ---- stage 2: load logical i+64r via S2; post-twiddle; store inter[] m-order
    {
        const u64* fbq = (const u64*)fb;
        #pragma unroll
        for (int r = 0; r < 8; r++)
            v[r] = fbq[(i ^ (8 * (r & 1))) + 64 * r];
    }
    asm volatile("bar.sync %0, 64;" :: "r"(fid + 1) : "memory");
    dft8_pk(v);
    {
        // recompute base twiddle here (was carried from input: costs 2 live regs)
        float bs2, bc2;
        __sincosf(-6.283185307179586f * ((float)i + 0.125f) * (1.0f / 2048.0f), &bs2, &bc2);
        const float2 base2 = make_float2(bc2, bs2);
        u64* fbq = (u64*)fb;
        #pragma unroll
        for (int rp = 0; rp < 8; rp++) {
            float2 tw = cmulf(base2, SP[rp]);
            fbq[i + 64 * rp] = cmul_pk(v[BR[rp]], tw);
        }
    }

    // ---- output constants (late, short live ranges) ----
    const bool odd = (tid & 1) != 0;
    const float inv = 1.0f / 512.0f;
    float w0 = win[tid]        * inv;
    float w1 = win[tid + 512]  * inv;
    float w2 = win[tid + 1024] * inv;
    float w3 = win[tid + 1536] * inv;
    const float wA0 = odd ? -w2 : w2;
    const float wA1 = odd ?  w3 : -w3;
    const float wB0 = odd ? -w0 : w0;
    const float wB1 = odd ? -w1 : w1;
    const int mA0 = odd ? (511 - tid)  : (513 + tid);
    const int mA1 = odd ? (1024 - tid) : tid;
    const int mB0 = odd ? (512 - tid)  : (512 + tid);
    const int mB1 = odd ? (1023 - tid) : (tid + 1);

    __syncthreads();

    // ---- output: chunk c -> out[t0+c][r] = inter_c[mA]*wA + inter_{c+1}[mB]*wB
    {
        const float* bse = (const float*)fbuf;   // frame f at bse + f*1024
        float* op = out + (size_t)b * OUTW + (size_t)t0 * 1024 + tid;
        #pragma unroll
        for (int c = 0; c < 7; c++) {
            if (t0 + c > 1022) break;
            const float* f0 = bse + c * 1024;
            const float* f1 = bse + (c + 1) * 1024;
            op[0]   = f0[mA0] * wA0 + f1[mB0] * wB0;
            op[512] = f0[mA1] * wA1 + f1[mB1] * wB1;
            op += 1024;
        }
    }
}

extern "C" void kernel_launch(void* const* d_in, const int* in_sizes, int n_in,
                              void* d_out, int out_size) {
    const float* sig = (const float*)d_in[0];
    const float* win = (const float*)d_in[1];
    float* out = (float*)d_out;
    dim3 grid(147, 32);   // 147*7 = 1029 >= 1023 chunks
    imdct_kernel<<<grid, 512>>>(sig, win, out);
}